// round 15
// baseline (speedup 1.0000x reference)
#include <cuda_runtime.h>
#include <cstdint>

// ---------------- problem constants ----------------
#define Bn   64
#define Cn   512
#define Pn   64
#define Kn   100
#define H1n  64
#define HIDn 128
#define Ln   32
#define CLIPV 100.0f
#define REDV (-0.1f)
#define PUSHT 10000.0f

typedef unsigned int u32;

// ---------------- device scratch (bf16 fragment layouts) ----------------
__device__ uint4 xF[(size_t)256 * 32 * 32];
__device__ uint4 w1F[(size_t)Kn * 32 * 4 * 32];
__device__ uint4 w2F[(size_t)Kn * 4 * 8 * 32];
__device__ uint4 w3F[(size_t)Kn * 8 * 2 * 32];
__device__ float f_dev[Kn * Bn];
__device__ float f1_dev[Kn * Bn];
__device__ unsigned int done_ctr = 0;

// ---------------- smem regions (bytes), 17.5KB -> 4 CTAs/SM + big L1 carveout ----------------
#define PS0     0          // 8KB fp32 [32][64] prototype 0
#define PS1     8192       // 8KB prototype 1
#define ERS     16384      // ers[128], er1s[128] = 1KB
#define SMEM_BYTES 17408

// ---------------- helpers ----------------
__device__ __forceinline__ u32 smem_u32(const void* p) {
    u32 a;
    asm("{ .reg .u64 t; cvta.to.shared.u64 t, %1; cvt.u32.u64 %0, t; }" : "=r"(a) : "l"(p));
    return a;
}
__device__ __forceinline__ float tanh_fast(float x) {
    float y; asm("tanh.approx.f32 %0, %1;" : "=f"(y) : "f"(x)); return y;
}
// pack two floats to bf16x2: lo -> bits[15:0], hi -> bits[31:16]
__device__ __forceinline__ u32 pk(float lo, float hi) {
    u32 r; asm("cvt.rn.bf16x2.f32 %0, %1, %2;" : "=r"(r) : "f"(hi), "f"(lo)); return r;
}
__device__ __forceinline__ void mma_bf16(float* d, uint4 a, u32 b0, u32 b1) {
    asm volatile(
        "mma.sync.aligned.m16n8k16.row.col.f32.bf16.bf16.f32 "
        "{%0,%1,%2,%3}, {%4,%5,%6,%7}, {%8,%9}, {%0,%1,%2,%3};"
        : "+f"(d[0]), "+f"(d[1]), "+f"(d[2]), "+f"(d[3])
        : "r"(a.x), "r"(a.y), "r"(a.z), "r"(a.w), "r"(b0), "r"(b1));
}
// D-frag (4 floats x 2 adjacent n8-tiles) -> next-stage A-frag, with tanh
__device__ __forceinline__ uint4 dfrag_to_afrag(const float* dE, const float* dO) {
    uint4 a;
    a.x = pk(tanh_fast(dE[0]), tanh_fast(dE[1]));
    a.y = pk(tanh_fast(dE[2]), tanh_fast(dE[3]));
    a.z = pk(tanh_fast(dO[0]), tanh_fast(dO[1]));
    a.w = pk(tanh_fast(dO[2]), tanh_fast(dO[3]));
    return a;
}
#define CP16(saddr, gptr) \
    asm volatile("cp.async.cg.shared.global [%0], [%1], 16;" :: "r"(saddr), "l"(gptr) : "memory")
#define CP_COMMIT() asm volatile("cp.async.commit_group;" ::: "memory")
#define CP_WAIT(n)  asm volatile("cp.async.wait_group %0;" :: "n"(n) : "memory")

// ================= fused permute kernel (x, W1, W2, W3 in one launch) =================
__global__ __launch_bounds__(256) void permute_all(const float* __restrict__ x,
                                                   const float* __restrict__ W1,
                                                   const float* __restrict__ W2,
                                                   const float* __restrict__ W3)
{
    __shared__ float t[64][65];
    const int bid = blockIdx.x;
    const int tid = threadIdx.x;

    if (bid < 512) {
        const int b = bid >> 3, cg = bid & 7;
        #pragma unroll
        for (int i = 0; i < 4; i++) {
            int idx = tid + i * 256;
            int cc = idx >> 4, p4 = (idx & 15) * 4;
            float4 v = *(const float4*)(x + ((size_t)(b * Cn + cg * 64 + cc)) * Pn + p4);
            t[cc][p4 + 0] = v.x; t[cc][p4 + 1] = v.y; t[cc][p4 + 2] = v.z; t[cc][p4 + 3] = v.w;
        }
        __syncthreads();
        #pragma unroll
        for (int i = 0; i < 2; i++) {
            int o = tid + i * 256;
            int lane = o & 31, kbl = (o >> 5) & 3, Rl = (o >> 7) & 3;
            int g = lane >> 2, tt = lane & 3;
            int c0 = kbl * 16 + 2 * tt, pA = Rl * 16 + g;
            uint4 v;
            v.x = pk(t[c0][pA],         t[c0 + 1][pA]);
            v.y = pk(t[c0][pA + 8],     t[c0 + 1][pA + 8]);
            v.z = pk(t[c0 + 8][pA],     t[c0 + 9][pA]);
            v.w = pk(t[c0 + 8][pA + 8], t[c0 + 9][pA + 8]);
            xF[((size_t)(b * 4 + Rl) * 32 + cg * 4 + kbl) * 32 + lane] = v;
        }
    } else if (bid < 2112) {
        int id = (bid - 512) * 256 + tid;
        int lane = id & 31, np = (id >> 5) & 3, kb = (id >> 7) & 31, k = id >> 12;
        int g = lane >> 2, tt = lane & 3;
        int o0 = np * 16 + g, o1 = o0 + 8, c = kb * 16 + 2 * tt;
        const float* W = W1 + (size_t)k * H1n * Cn;
        uint4 v;
        v.x = pk(W[(size_t)o0 * Cn + c],     W[(size_t)o0 * Cn + c + 1]);
        v.y = pk(W[(size_t)o0 * Cn + c + 8], W[(size_t)o0 * Cn + c + 9]);
        v.z = pk(W[(size_t)o1 * Cn + c],     W[(size_t)o1 * Cn + c + 1]);
        v.w = pk(W[(size_t)o1 * Cn + c + 8], W[(size_t)o1 * Cn + c + 9]);
        w1F[id] = v;
    } else if (bid < 2512) {
        int id = (bid - 2112) * 256 + tid;
        int lane = id & 31, np = (id >> 5) & 7, kb = (id >> 8) & 3, k = id >> 10;
        int g = lane >> 2, tt = lane & 3;
        int o0 = np * 16 + g, o1 = o0 + 8, c = kb * 16 + 2 * tt;
        const float* W = W2 + (size_t)k * HIDn * H1n;
        uint4 v;
        v.x = pk(W[(size_t)o0 * H1n + c],     W[(size_t)o0 * H1n + c + 1]);
        v.y = pk(W[(size_t)o0 * H1n + c + 8], W[(size_t)o0 * H1n + c + 9]);
        v.z = pk(W[(size_t)o1 * H1n + c],     W[(size_t)o1 * H1n + c + 1]);
        v.w = pk(W[(size_t)o1 * H1n + c + 8], W[(size_t)o1 * H1n + c + 9]);
        w2F[id] = v;
    } else {
        int id = (bid - 2512) * 256 + tid;
        int lane = id & 31, np = (id >> 5) & 1, kb = (id >> 6) & 7, k = id >> 9;
        int g = lane >> 2, tt = lane & 3;
        int o0 = np * 16 + g, o1 = o0 + 8, c = kb * 16 + 2 * tt;
        const float* W = W3 + (size_t)k * Ln * HIDn;
        uint4 v;
        v.x = pk(W[(size_t)o0 * HIDn + c],     W[(size_t)o0 * HIDn + c + 1]);
        v.y = pk(W[(size_t)o0 * HIDn + c + 8], W[(size_t)o0 * HIDn + c + 9]);
        v.z = pk(W[(size_t)o1 * HIDn + c],     W[(size_t)o1 * HIDn + c + 1]);
        v.w = pk(W[(size_t)o1 * HIDn + c + 8], W[(size_t)o1 * HIDn + c + 9]);
        w3F[id] = v;
    }
}

// ================= main fused kernel: 128 threads, 4 warps, 4 CTAs/SM, 2 j-tiles/CTA =========
__global__ __launch_bounds__(128, 4)
void fused_main(const int* __restrict__ ycls, const float* __restrict__ pr0,
                const float* __restrict__ pr1, float* __restrict__ out)
{
    extern __shared__ char smb[];
    const u32 smu = smem_u32(smb);
    const int k     = blockIdx.y;
    const int tid   = threadIdx.x;
    const int lane  = tid & 31;
    const int warp  = tid >> 5;
    const int g     = lane >> 2;
    const int tt    = lane & 3;

    // ---- prologue cp.async (ONE group): prototype tiles (shared by both j-tiles) ----
    {
        const float* p0k = pr0 + (size_t)k * Ln * Pn;
        const float* p1k = pr1 + (size_t)k * Ln * Pn;
        #pragma unroll
        for (int i = 0; i < 4; i++) {
            CP16(smu + PS0 + (tid + i * 128) * 16, p0k + (tid + i * 128) * 4);
            CP16(smu + PS1 + (tid + i * 128) * 16, p1k + (tid + i * 128) * 4);
        }
        CP_COMMIT();
    }

    const uint4* w1p = w1F + (size_t)k * 4096;   // [kb][np][lane]
    const uint4* w2p = w2F + (size_t)k * 1024;   // ((kb*8+s)*32+lane)
    const uint4* w3p = w3F + (size_t)k * 512;    // ((s*2+t)*32+lane)

    bool waited = false;

    #pragma unroll 1
    for (int jj = 0; jj < 2; jj++) {
        const int jtile = blockIdx.x * 2 + jj;
        const int jbase = jtile * 128;
        const int b0    = jtile * 2;

        // ============= Stage A: M=32/warp, N=64, K=512, barrier-free, all-LDG =============
        const int R0 = jtile * 8 + warp * 2, R1 = R0 + 1;
        float accA[8][2][4];
        #pragma unroll
        for (int n = 0; n < 8; n++)
            #pragma unroll
            for (int r = 0; r < 2; r++)
                #pragma unroll
                for (int q = 0; q < 4; q++) accA[n][r][q] = 0.f;

        // double-buffered A and B fragments (slot = kb & 1), distance-1 prefetch
        uint4 aC[2][2];
        uint4 bC[2][4];
        aC[0][0] = xF[((size_t)R0 * 32 + 0) * 32 + lane];
        aC[0][1] = xF[((size_t)R1 * 32 + 0) * 32 + lane];
        #pragma unroll
        for (int np = 0; np < 4; np++) bC[0][np] = w1p[(0 * 4 + np) * 32 + lane];

        #pragma unroll
        for (int kb = 0; kb < 32; kb++) {
            const int sl = kb & 1, ns = sl ^ 1;
            if (kb < 31) {
                aC[ns][0] = xF[((size_t)R0 * 32 + kb + 1) * 32 + lane];
                aC[ns][1] = xF[((size_t)R1 * 32 + kb + 1) * 32 + lane];
                #pragma unroll
                for (int np = 0; np < 4; np++) bC[ns][np] = w1p[((kb + 1) * 4 + np) * 32 + lane];
            }
            #pragma unroll
            for (int np = 0; np < 4; np++) {
                mma_bf16(accA[2 * np][0],     aC[sl][0], bC[sl][np].x, bC[sl][np].y);
                mma_bf16(accA[2 * np][1],     aC[sl][1], bC[sl][np].x, bC[sl][np].y);
                mma_bf16(accA[2 * np + 1][0], aC[sl][0], bC[sl][np].z, bC[sl][np].w);
                mma_bf16(accA[2 * np + 1][1], aC[sl][1], bC[sl][np].z, bC[sl][np].w);
            }
        }

        // ---- h1 A-frags in registers ----
        uint4 h1f[2][4];                             // [rt][kb] over K=64
        #pragma unroll
        for (int rt = 0; rt < 2; rt++)
            #pragma unroll
            for (int kb = 0; kb < 4; kb++)
                h1f[rt][kb] = dfrag_to_afrag(accA[2 * kb][rt], accA[2 * kb + 1][rt]);

        // ============= Stages B+C fused: 8 N=16 slices, direct-LDG W2/W3 =============
        float accC[4][2][4];
        #pragma unroll
        for (int n = 0; n < 4; n++)
            #pragma unroll
            for (int r = 0; r < 2; r++)
                #pragma unroll
                for (int q = 0; q < 4; q++) accC[n][r][q] = 0.f;

        #pragma unroll
        for (int s = 0; s < 8; s++) {
            float accB[2][2][4];
            #pragma unroll
            for (int n = 0; n < 2; n++)
                #pragma unroll
                for (int r = 0; r < 2; r++)
                    #pragma unroll
                    for (int q = 0; q < 4; q++) accB[n][r][q] = 0.f;
            #pragma unroll
            for (int kb = 0; kb < 4; kb++) {
                uint4 bv = w2p[((size_t)(kb * 8 + s)) * 32 + lane];
                #pragma unroll
                for (int rt = 0; rt < 2; rt++) {
                    mma_bf16(accB[0][rt], h1f[rt][kb], bv.x, bv.y);
                    mma_bf16(accB[1][rt], h1f[rt][kb], bv.z, bv.w);
                }
            }
            uint4 bw0 = w3p[((size_t)(s * 2 + 0)) * 32 + lane];
            uint4 bw1 = w3p[((size_t)(s * 2 + 1)) * 32 + lane];
            #pragma unroll
            for (int rt = 0; rt < 2; rt++) {
                uint4 af = dfrag_to_afrag(accB[0][rt], accB[1][rt]);
                mma_bf16(accC[0][rt], af, bw0.x, bw0.y);
                mma_bf16(accC[1][rt], af, bw0.z, bw0.w);
                mma_bf16(accC[2][rt], af, bw1.x, bw1.y);
                mma_bf16(accC[3][rt], af, bw1.z, bw1.w);
            }
        }

        // ---- sync: protos landed (first tile) / prior ers reads done (both tiles) ----
        if (!waited) { CP_WAIT(0); waited = true; }
        __syncthreads();

        // ---- epilogue: tanh, distances, clip, logits, per-(k,b) sums ----
        {
            const float* ps0 = (const float*)(smb + PS0);   // [32][64] fp32
            const float* ps1 = (const float*)(smb + PS1);
            float* ers  = (float*)(smb + ERS);
            float* er1s = ers + 128;
            #pragma unroll
            for (int rt = 0; rt < 2; rt++) {
                #pragma unroll
                for (int half = 0; half < 2; half++) {
                    int lr = warp * 32 + rt * 16 + g + half * 8;
                    int p  = (jbase + lr) & 63;
                    float d0 = 0.f, d1 = 0.f;
                    #pragma unroll
                    for (int n0 = 0; n0 < 4; n0++) {
                        int c0 = n0 * 8 + 2 * tt, c1 = c0 + 1;
                        float v0 = tanh_fast(accC[n0][rt][half * 2 + 0]);
                        float v1 = tanh_fast(accC[n0][rt][half * 2 + 1]);
                        float q;
                        q = v0 - ps0[c0 * 64 + p]; d0 += q * q;
                        q = v1 - ps0[c1 * 64 + p]; d0 += q * q;
                        q = v0 - ps1[c0 * 64 + p]; d1 += q * q;
                        q = v1 - ps1[c1 * 64 + p]; d1 += q * q;
                    }
                    d0 += __shfl_xor_sync(0xFFFFFFFFu, d0, 1);
                    d0 += __shfl_xor_sync(0xFFFFFFFFu, d0, 2);
                    d1 += __shfl_xor_sync(0xFFFFFFFFu, d1, 1);
                    d1 += __shfl_xor_sync(0xFFFFFFFFu, d1, 2);
                    if (tt == 0) {
                        float er  = fminf(fmaxf(d0 * REDV, -CLIPV), CLIPV);
                        float er1 = fminf(fmaxf(d1 * REDV, -CLIPV), CLIPV);
                        int b = b0 + (lr >> 6);
                        out[((size_t)b * Kn + k) * Pn + p] = er;
                        out[(size_t)Bn * Kn * Pn + ((size_t)b * Kn + k) * Pn + p] = er1;
                        ers[lr]  = er;
                        er1s[lr] = er1;
                    }
                }
            }
        }
        __syncthreads();
        // ---- warp-parallel per-(k,b) sums ----
        if (warp < 4) {
            const float* src = (float*)(smb + ERS) + ((warp < 2) ? 0 : 128) + (warp & 1) * 64;
            float s = src[lane] + src[lane + 32];
            #pragma unroll
            for (int m = 16; m > 0; m >>= 1) s += __shfl_xor_sync(0xFFFFFFFFu, s, m);
            if (lane == 0) {
                if (warp < 2) f_dev[k * Bn + b0 + (warp & 1)]  = s;
                else          f1_dev[k * Bn + b0 + (warp & 1)] = s;
            }
        }
    }
    __syncthreads();

    // ---- last-CTA finalize: pull/push ----
    __threadfence();
    __shared__ u32 s_is_last;
    if (tid == 0) {
        u32 old = atomicAdd(&done_ctr, 1u);
        s_is_last = (old == gridDim.x * gridDim.y - 1) ? 1u : 0u;
    }
    __syncthreads();
    if (s_is_last) {
        __threadfence();
        float* s_pull = (float*)smb;
        float* s_push = s_pull + 128;
        float pull = 0.f, push = 0.f;
        if (tid < Kn) {
            float se = 0.f, sc = 0.f;
            int ne = 0, nc = 0;
            #pragma unroll 8
            for (int b = 0; b < Bn; b++) {
                float fv  = __ldcg(&f_dev[tid * Bn + b]);
                float f1v = __ldcg(&f1_dev[tid * Bn + b]);
                if (ycls[b] == tid) { se += f1v; ne++; }
                else if (fv < PUSHT) { sc += fv; nc++; }
            }
            if (ne > 0) pull = se / (float)ne;
            if (nc > 0) push = sc / (float)nc;
        }
        s_pull[tid] = pull;
        s_push[tid] = push;
        __syncthreads();
        for (int s = 64; s > 0; s >>= 1) {
            if (tid < s) { s_pull[tid] += s_pull[tid + s]; s_push[tid] += s_push[tid + s]; }
            __syncthreads();
        }
        if (tid == 0) {
            size_t base = (size_t)2 * Bn * Kn * Pn;
            out[base]     = s_pull[0];
            out[base + 1] = s_push[0];
            done_ctr = 0;   // deterministic across graph replays
        }
    }
}

extern "C" void kernel_launch(void* const* d_in, const int* in_sizes, int n_in,
                              void* d_out, int out_size)
{
    const float* x    = (const float*)d_in[0];
    const int*   ycls = (const int*)  d_in[1];
    const float* W1   = (const float*)d_in[4];
    const float* W2   = (const float*)d_in[5];
    const float* W3   = (const float*)d_in[6];
    const float* pr0  = (const float*)d_in[7];
    const float* pr1  = (const float*)d_in[8];
    float* out = (float*)d_out;

    permute_all<<<2712, 256>>>(x, W1, W2, W3);

    cudaFuncSetAttribute(fused_main, cudaFuncAttributeMaxDynamicSharedMemorySize, SMEM_BYTES);
    fused_main<<<dim3(16, Kn), 128, SMEM_BYTES>>>(ycls, pr0, pr1, out);
}

// round 16
// speedup vs baseline: 1.0738x; 1.0738x over previous
#include <cuda_runtime.h>
#include <cstdint>

// ---------------- problem constants ----------------
#define Bn   64
#define Cn   512
#define Pn   64
#define Kn   100
#define H1n  64
#define HIDn 128
#define Ln   32
#define CLIPV 100.0f
#define REDV (-0.1f)
#define PUSHT 10000.0f

typedef unsigned int u32;

// ---------------- device scratch (bf16 fragment layouts) ----------------
__device__ uint4 xF[(size_t)256 * 32 * 32];
__device__ uint4 w1F[(size_t)Kn * 32 * 4 * 32];
__device__ uint4 w2F[(size_t)Kn * 4 * 8 * 32];
__device__ uint4 w3F[(size_t)Kn * 8 * 2 * 32];
__device__ float f_dev[Kn * Bn];
__device__ float f1_dev[Kn * Bn];
__device__ unsigned int done_ctr = 0;

// ---------------- smem regions (bytes), 17.5KB -> 4 CTAs/SM + big L1 carveout ----------------
#define PS0     0          // 8KB fp32 [32][64] prototype 0
#define PS1     8192       // 8KB prototype 1
#define ERS     16384      // ers[128], er1s[128] = 1KB
#define SMEM_BYTES 17408

// ---------------- helpers ----------------
__device__ __forceinline__ u32 smem_u32(const void* p) {
    u32 a;
    asm("{ .reg .u64 t; cvta.to.shared.u64 t, %1; cvt.u32.u64 %0, t; }" : "=r"(a) : "l"(p));
    return a;
}
__device__ __forceinline__ float tanh_fast(float x) {
    float y; asm("tanh.approx.f32 %0, %1;" : "=f"(y) : "f"(x)); return y;
}
// pack two floats to bf16x2: lo -> bits[15:0], hi -> bits[31:16]
__device__ __forceinline__ u32 pk(float lo, float hi) {
    u32 r; asm("cvt.rn.bf16x2.f32 %0, %1, %2;" : "=r"(r) : "f"(hi), "f"(lo)); return r;
}
// L1-bypass (cache-global) uint4 load: keeps streaming xF out of L1
__device__ __forceinline__ uint4 ldg_cg(const uint4* p) {
    uint4 v;
    asm volatile("ld.global.cg.v4.u32 {%0,%1,%2,%3}, [%4];"
                 : "=r"(v.x), "=r"(v.y), "=r"(v.z), "=r"(v.w) : "l"(p));
    return v;
}
__device__ __forceinline__ void mma_bf16(float* d, uint4 a, u32 b0, u32 b1) {
    asm volatile(
        "mma.sync.aligned.m16n8k16.row.col.f32.bf16.bf16.f32 "
        "{%0,%1,%2,%3}, {%4,%5,%6,%7}, {%8,%9}, {%0,%1,%2,%3};"
        : "+f"(d[0]), "+f"(d[1]), "+f"(d[2]), "+f"(d[3])
        : "r"(a.x), "r"(a.y), "r"(a.z), "r"(a.w), "r"(b0), "r"(b1));
}
// D-frag (4 floats x 2 adjacent n8-tiles) -> next-stage A-frag, with tanh
__device__ __forceinline__ uint4 dfrag_to_afrag(const float* dE, const float* dO) {
    uint4 a;
    a.x = pk(tanh_fast(dE[0]), tanh_fast(dE[1]));
    a.y = pk(tanh_fast(dE[2]), tanh_fast(dE[3]));
    a.z = pk(tanh_fast(dO[0]), tanh_fast(dO[1]));
    a.w = pk(tanh_fast(dO[2]), tanh_fast(dO[3]));
    return a;
}
#define CP16(saddr, gptr) \
    asm volatile("cp.async.cg.shared.global [%0], [%1], 16;" :: "r"(saddr), "l"(gptr) : "memory")
#define CP_COMMIT() asm volatile("cp.async.commit_group;" ::: "memory")
#define CP_WAIT(n)  asm volatile("cp.async.wait_group %0;" :: "n"(n) : "memory")

// ================= fused permute kernel (x, W1, W2, W3 in one launch) =================
__global__ __launch_bounds__(256) void permute_all(const float* __restrict__ x,
                                                   const float* __restrict__ W1,
                                                   const float* __restrict__ W2,
                                                   const float* __restrict__ W3)
{
    __shared__ float t[64][65];
    const int bid = blockIdx.x;
    const int tid = threadIdx.x;

    if (bid < 512) {
        const int b = bid >> 3, cg = bid & 7;
        #pragma unroll
        for (int i = 0; i < 4; i++) {
            int idx = tid + i * 256;
            int cc = idx >> 4, p4 = (idx & 15) * 4;
            float4 v = *(const float4*)(x + ((size_t)(b * Cn + cg * 64 + cc)) * Pn + p4);
            t[cc][p4 + 0] = v.x; t[cc][p4 + 1] = v.y; t[cc][p4 + 2] = v.z; t[cc][p4 + 3] = v.w;
        }
        __syncthreads();
        #pragma unroll
        for (int i = 0; i < 2; i++) {
            int o = tid + i * 256;
            int lane = o & 31, kbl = (o >> 5) & 3, Rl = (o >> 7) & 3;
            int g = lane >> 2, tt = lane & 3;
            int c0 = kbl * 16 + 2 * tt, pA = Rl * 16 + g;
            uint4 v;
            v.x = pk(t[c0][pA],         t[c0 + 1][pA]);
            v.y = pk(t[c0][pA + 8],     t[c0 + 1][pA + 8]);
            v.z = pk(t[c0 + 8][pA],     t[c0 + 9][pA]);
            v.w = pk(t[c0 + 8][pA + 8], t[c0 + 9][pA + 8]);
            xF[((size_t)(b * 4 + Rl) * 32 + cg * 4 + kbl) * 32 + lane] = v;
        }
    } else if (bid < 2112) {
        int id = (bid - 512) * 256 + tid;
        int lane = id & 31, np = (id >> 5) & 3, kb = (id >> 7) & 31, k = id >> 12;
        int g = lane >> 2, tt = lane & 3;
        int o0 = np * 16 + g, o1 = o0 + 8, c = kb * 16 + 2 * tt;
        const float* W = W1 + (size_t)k * H1n * Cn;
        uint4 v;
        v.x = pk(W[(size_t)o0 * Cn + c],     W[(size_t)o0 * Cn + c + 1]);
        v.y = pk(W[(size_t)o0 * Cn + c + 8], W[(size_t)o0 * Cn + c + 9]);
        v.z = pk(W[(size_t)o1 * Cn + c],     W[(size_t)o1 * Cn + c + 1]);
        v.w = pk(W[(size_t)o1 * Cn + c + 8], W[(size_t)o1 * Cn + c + 9]);
        w1F[id] = v;
    } else if (bid < 2512) {
        int id = (bid - 2112) * 256 + tid;
        int lane = id & 31, np = (id >> 5) & 7, kb = (id >> 8) & 3, k = id >> 10;
        int g = lane >> 2, tt = lane & 3;
        int o0 = np * 16 + g, o1 = o0 + 8, c = kb * 16 + 2 * tt;
        const float* W = W2 + (size_t)k * HIDn * H1n;
        uint4 v;
        v.x = pk(W[(size_t)o0 * H1n + c],     W[(size_t)o0 * H1n + c + 1]);
        v.y = pk(W[(size_t)o0 * H1n + c + 8], W[(size_t)o0 * H1n + c + 9]);
        v.z = pk(W[(size_t)o1 * H1n + c],     W[(size_t)o1 * H1n + c + 1]);
        v.w = pk(W[(size_t)o1 * H1n + c + 8], W[(size_t)o1 * H1n + c + 9]);
        w2F[id] = v;
    } else {
        int id = (bid - 2512) * 256 + tid;
        int lane = id & 31, np = (id >> 5) & 1, kb = (id >> 6) & 7, k = id >> 9;
        int g = lane >> 2, tt = lane & 3;
        int o0 = np * 16 + g, o1 = o0 + 8, c = kb * 16 + 2 * tt;
        const float* W = W3 + (size_t)k * Ln * HIDn;
        uint4 v;
        v.x = pk(W[(size_t)o0 * HIDn + c],     W[(size_t)o0 * HIDn + c + 1]);
        v.y = pk(W[(size_t)o0 * HIDn + c + 8], W[(size_t)o0 * HIDn + c + 9]);
        v.z = pk(W[(size_t)o1 * HIDn + c],     W[(size_t)o1 * HIDn + c + 1]);
        v.w = pk(W[(size_t)o1 * HIDn + c + 8], W[(size_t)o1 * HIDn + c + 9]);
        w3F[id] = v;
    }
}

// ================= main fused kernel: 128 threads, 4 warps, 4 CTAs/SM =================
__global__ __launch_bounds__(128, 4)
void fused_main(const int* __restrict__ ycls, const float* __restrict__ pr0,
                const float* __restrict__ pr1, float* __restrict__ out)
{
    extern __shared__ char smb[];
    const u32 smu = smem_u32(smb);
    const int k     = blockIdx.y;
    const int jtile = blockIdx.x;
    const int jbase = jtile * 128;
    const int b0    = jtile * 2;
    const int tid   = threadIdx.x;
    const int lane  = tid & 31;
    const int warp  = tid >> 5;
    const int g     = lane >> 2;
    const int tt    = lane & 3;

    // ---- prologue cp.async (ONE group): prototype tiles only ----
    {
        const float* p0k = pr0 + (size_t)k * Ln * Pn;
        const float* p1k = pr1 + (size_t)k * Ln * Pn;
        #pragma unroll
        for (int i = 0; i < 4; i++) {
            CP16(smu + PS0 + (tid + i * 128) * 16, p0k + (tid + i * 128) * 4);
            CP16(smu + PS1 + (tid + i * 128) * 16, p1k + (tid + i * 128) * 4);
        }
        CP_COMMIT();
    }

    // ================= Stage A: M=32/warp, N=64, K=512, barrier-free, all-LDG =================
    const int R0 = jtile * 8 + warp * 2, R1 = R0 + 1;
    const uint4* w1p = w1F + (size_t)k * 4096;   // [kb][np][lane] fragment uint4s
    float accA[8][2][4];
    #pragma unroll
    for (int n = 0; n < 8; n++)
        #pragma unroll
        for (int r = 0; r < 2; r++)
            #pragma unroll
            for (int q = 0; q < 4; q++) accA[n][r][q] = 0.f;

    // double-buffered A and B fragments (slot = kb & 1), distance-1 prefetch
    // xF loads use .cg (L1-bypass): streamed once per CTA, would otherwise evict
    // the W-fragment lines that sibling warps re-read from L1.
    uint4 aC[2][2];
    uint4 bC[2][4];
    aC[0][0] = ldg_cg(&xF[((size_t)R0 * 32 + 0) * 32 + lane]);
    aC[0][1] = ldg_cg(&xF[((size_t)R1 * 32 + 0) * 32 + lane]);
    #pragma unroll
    for (int np = 0; np < 4; np++) bC[0][np] = w1p[(0 * 4 + np) * 32 + lane];

    #pragma unroll
    for (int kb = 0; kb < 32; kb++) {
        const int sl = kb & 1, ns = sl ^ 1;
        if (kb < 31) {
            aC[ns][0] = ldg_cg(&xF[((size_t)R0 * 32 + kb + 1) * 32 + lane]);
            aC[ns][1] = ldg_cg(&xF[((size_t)R1 * 32 + kb + 1) * 32 + lane]);
            #pragma unroll
            for (int np = 0; np < 4; np++) bC[ns][np] = w1p[((kb + 1) * 4 + np) * 32 + lane];
        }
        #pragma unroll
        for (int np = 0; np < 4; np++) {
            mma_bf16(accA[2 * np][0],     aC[sl][0], bC[sl][np].x, bC[sl][np].y);
            mma_bf16(accA[2 * np][1],     aC[sl][1], bC[sl][np].x, bC[sl][np].y);
            mma_bf16(accA[2 * np + 1][0], aC[sl][0], bC[sl][np].z, bC[sl][np].w);
            mma_bf16(accA[2 * np + 1][1], aC[sl][1], bC[sl][np].z, bC[sl][np].w);
        }
    }

    // ---- h1 A-frags in registers ----
    uint4 h1f[2][4];                             // [rt][kb] over K=64
    #pragma unroll
    for (int rt = 0; rt < 2; rt++)
        #pragma unroll
        for (int kb = 0; kb < 4; kb++)
            h1f[rt][kb] = dfrag_to_afrag(accA[2 * kb][rt], accA[2 * kb + 1][rt]);

    // ================= Stages B+C fused: 8 N=16 slices, direct-LDG W2/W3, no barriers ==========
    const uint4* w2p = w2F + (size_t)k * 1024;   // ((kb*8+s)*32+lane)
    const uint4* w3p = w3F + (size_t)k * 512;    // ((s*2+t)*32+lane)
    float accC[4][2][4];
    #pragma unroll
    for (int n = 0; n < 4; n++)
        #pragma unroll
        for (int r = 0; r < 2; r++)
            #pragma unroll
            for (int q = 0; q < 4; q++) accC[n][r][q] = 0.f;

    #pragma unroll
    for (int s = 0; s < 8; s++) {
        // ---- stage B slice: N=16 (h2 cols [16s,16s+16)), K=64 ----
        float accB[2][2][4];
        #pragma unroll
        for (int n = 0; n < 2; n++)
            #pragma unroll
            for (int r = 0; r < 2; r++)
                #pragma unroll
                for (int q = 0; q < 4; q++) accB[n][r][q] = 0.f;
        #pragma unroll
        for (int kb = 0; kb < 4; kb++) {
            uint4 bv = w2p[((size_t)(kb * 8 + s)) * 32 + lane];
            #pragma unroll
            for (int rt = 0; rt < 2; rt++) {
                mma_bf16(accB[0][rt], h1f[rt][kb], bv.x, bv.y);
                mma_bf16(accB[1][rt], h1f[rt][kb], bv.z, bv.w);
            }
        }
        // ---- pack slice as stage-C A-frag (K-chunk s) and accumulate C ----
        uint4 bw0 = w3p[((size_t)(s * 2 + 0)) * 32 + lane];
        uint4 bw1 = w3p[((size_t)(s * 2 + 1)) * 32 + lane];
        #pragma unroll
        for (int rt = 0; rt < 2; rt++) {
            uint4 af = dfrag_to_afrag(accB[0][rt], accB[1][rt]);
            mma_bf16(accC[0][rt], af, bw0.x, bw0.y);
            mma_bf16(accC[1][rt], af, bw0.z, bw0.w);
            mma_bf16(accC[2][rt], af, bw1.x, bw1.y);
            mma_bf16(accC[3][rt], af, bw1.z, bw1.w);
        }
    }

    // ---- first synchronization of the whole kernel: protos landed + visible ----
    CP_WAIT(0);
    __syncthreads();

    // ---- epilogue C: tanh, distances, clip, logits, per-(k,b) sums ----
    {
        const float* ps0 = (const float*)(smb + PS0);   // [32][64] fp32
        const float* ps1 = (const float*)(smb + PS1);
        float* ers  = (float*)(smb + ERS);
        float* er1s = ers + 128;
        #pragma unroll
        for (int rt = 0; rt < 2; rt++) {
            #pragma unroll
            for (int half = 0; half < 2; half++) {
                int lr = warp * 32 + rt * 16 + g + half * 8;
                int p  = (jbase + lr) & 63;
                float d0 = 0.f, d1 = 0.f;
                #pragma unroll
                for (int n0 = 0; n0 < 4; n0++) {
                    int c0 = n0 * 8 + 2 * tt, c1 = c0 + 1;
                    float v0 = tanh_fast(accC[n0][rt][half * 2 + 0]);
                    float v1 = tanh_fast(accC[n0][rt][half * 2 + 1]);
                    float q;
                    q = v0 - ps0[c0 * 64 + p]; d0 += q * q;
                    q = v1 - ps0[c1 * 64 + p]; d0 += q * q;
                    q = v0 - ps1[c0 * 64 + p]; d1 += q * q;
                    q = v1 - ps1[c1 * 64 + p]; d1 += q * q;
                }
                d0 += __shfl_xor_sync(0xFFFFFFFFu, d0, 1);
                d0 += __shfl_xor_sync(0xFFFFFFFFu, d0, 2);
                d1 += __shfl_xor_sync(0xFFFFFFFFu, d1, 1);
                d1 += __shfl_xor_sync(0xFFFFFFFFu, d1, 2);
                if (tt == 0) {
                    float er  = fminf(fmaxf(d0 * REDV, -CLIPV), CLIPV);
                    float er1 = fminf(fmaxf(d1 * REDV, -CLIPV), CLIPV);
                    int b = b0 + (lr >> 6);
                    out[((size_t)b * Kn + k) * Pn + p] = er;
                    out[(size_t)Bn * Kn * Pn + ((size_t)b * Kn + k) * Pn + p] = er1;
                    ers[lr]  = er;
                    er1s[lr] = er1;
                }
            }
        }
    }
    __syncthreads();
    // ---- warp-parallel per-(k,b) sums: warp w -> (array = w<2 ? er : er1, b = b0 + (w&1)) ----
    if (warp < 4) {
        const float* src = (float*)(smb + ERS) + ((warp < 2) ? 0 : 128) + (warp & 1) * 64;
        float s = src[lane] + src[lane + 32];
        #pragma unroll
        for (int m = 16; m > 0; m >>= 1) s += __shfl_xor_sync(0xFFFFFFFFu, s, m);
        if (lane == 0) {
            if (warp < 2) f_dev[k * Bn + b0 + (warp & 1)]  = s;
            else          f1_dev[k * Bn + b0 + (warp & 1)] = s;
        }
    }
    __syncthreads();

    // ---- last-CTA finalize: pull/push ----
    __threadfence();
    __shared__ u32 s_is_last;
    if (tid == 0) {
        u32 old = atomicAdd(&done_ctr, 1u);
        s_is_last = (old == gridDim.x * gridDim.y - 1) ? 1u : 0u;
    }
    __syncthreads();
    if (s_is_last) {
        __threadfence();
        float* s_pull = (float*)smb;
        float* s_push = s_pull + 128;
        float pull = 0.f, push = 0.f;
        if (tid < Kn) {
            float se = 0.f, sc = 0.f;
            int ne = 0, nc = 0;
            #pragma unroll 8
            for (int b = 0; b < Bn; b++) {
                float fv  = __ldcg(&f_dev[tid * Bn + b]);
                float f1v = __ldcg(&f1_dev[tid * Bn + b]);
                if (ycls[b] == tid) { se += f1v; ne++; }
                else if (fv < PUSHT) { sc += fv; nc++; }
            }
            if (ne > 0) pull = se / (float)ne;
            if (nc > 0) push = sc / (float)nc;
        }
        s_pull[tid] = pull;
        s_push[tid] = push;
        __syncthreads();
        for (int s = 64; s > 0; s >>= 1) {
            if (tid < s) { s_pull[tid] += s_pull[tid + s]; s_push[tid] += s_push[tid + s]; }
            __syncthreads();
        }
        if (tid == 0) {
            size_t base = (size_t)2 * Bn * Kn * Pn;
            out[base]     = s_pull[0];
            out[base + 1] = s_push[0];
            done_ctr = 0;   // deterministic across graph replays
        }
    }
}

extern "C" void kernel_launch(void* const* d_in, const int* in_sizes, int n_in,
                              void* d_out, int out_size)
{
    const float* x    = (const float*)d_in[0];
    const int*   ycls = (const int*)  d_in[1];
    const float* W1   = (const float*)d_in[4];
    const float* W2   = (const float*)d_in[5];
    const float* W3   = (const float*)d_in[6];
    const float* pr0  = (const float*)d_in[7];
    const float* pr1  = (const float*)d_in[8];
    float* out = (float*)d_out;

    permute_all<<<2712, 256>>>(x, W1, W2, W3);

    cudaFuncSetAttribute(fused_main, cudaFuncAttributeMaxDynamicSharedMemorySize, SMEM_BYTES);
    fused_main<<<dim3(32, Kn), 128, SMEM_BYTES>>>(ycls, pr0, pr1, out);
}

// round 17
// speedup vs baseline: 1.0765x; 1.0025x over previous
#include <cuda_runtime.h>
#include <cstdint>

// ---------------- problem constants ----------------
#define Bn   64
#define Cn   512
#define Pn   64
#define Kn   100
#define H1n  64
#define HIDn 128
#define Ln   32
#define CLIPV 100.0f
#define REDV (-0.1f)
#define PUSHT 10000.0f

typedef unsigned int u32;

// ---------------- device scratch (bf16 fragment layouts) ----------------
__device__ uint4 xF[(size_t)256 * 32 * 32];
__device__ uint4 w1F[(size_t)Kn * 32 * 4 * 32];
__device__ uint4 w2F[(size_t)Kn * 4 * 8 * 32];
__device__ uint4 w3F[(size_t)Kn * 8 * 2 * 32];
__device__ float f_dev[Kn * Bn];
__device__ float f1_dev[Kn * Bn];
__device__ unsigned int done_ctr = 0;

// ---------------- smem regions (bytes), 17.5KB -> 4 CTAs/SM + big L1 carveout ----------------
#define PS0     0          // 8KB fp32 [32][64] prototype 0
#define PS1     8192       // 8KB prototype 1
#define ERS     16384      // ers[128], er1s[128] = 1KB
#define SMEM_BYTES 17408

// ---------------- helpers ----------------
__device__ __forceinline__ u32 smem_u32(const void* p) {
    u32 a;
    asm("{ .reg .u64 t; cvta.to.shared.u64 t, %1; cvt.u32.u64 %0, t; }" : "=r"(a) : "l"(p));
    return a;
}
__device__ __forceinline__ float tanh_fast(float x) {
    float y; asm("tanh.approx.f32 %0, %1;" : "=f"(y) : "f"(x)); return y;
}
// pack two floats to bf16x2: lo -> bits[15:0], hi -> bits[31:16]
__device__ __forceinline__ u32 pk(float lo, float hi) {
    u32 r; asm("cvt.rn.bf16x2.f32 %0, %1, %2;" : "=r"(r) : "f"(hi), "f"(lo)); return r;
}
// L1-bypass (cache-global) uint4 load: keeps streaming xF out of L1
__device__ __forceinline__ uint4 ldg_cg(const uint4* p) {
    uint4 v;
    asm volatile("ld.global.cg.v4.u32 {%0,%1,%2,%3}, [%4];"
                 : "=r"(v.x), "=r"(v.y), "=r"(v.z), "=r"(v.w) : "l"(p));
    return v;
}
__device__ __forceinline__ void mma_bf16(float* d, uint4 a, u32 b0, u32 b1) {
    asm volatile(
        "mma.sync.aligned.m16n8k16.row.col.f32.bf16.bf16.f32 "
        "{%0,%1,%2,%3}, {%4,%5,%6,%7}, {%8,%9}, {%0,%1,%2,%3};"
        : "+f"(d[0]), "+f"(d[1]), "+f"(d[2]), "+f"(d[3])
        : "r"(a.x), "r"(a.y), "r"(a.z), "r"(a.w), "r"(b0), "r"(b1));
}
// D-frag (4 floats x 2 adjacent n8-tiles) -> next-stage A-frag, with tanh
__device__ __forceinline__ uint4 dfrag_to_afrag(const float* dE, const float* dO) {
    uint4 a;
    a.x = pk(tanh_fast(dE[0]), tanh_fast(dE[1]));
    a.y = pk(tanh_fast(dE[2]), tanh_fast(dE[3]));
    a.z = pk(tanh_fast(dO[0]), tanh_fast(dO[1]));
    a.w = pk(tanh_fast(dO[2]), tanh_fast(dO[3]));
    return a;
}
#define CP16(saddr, gptr) \
    asm volatile("cp.async.cg.shared.global [%0], [%1], 16;" :: "r"(saddr), "l"(gptr) : "memory")
#define CP_COMMIT() asm volatile("cp.async.commit_group;" ::: "memory")
#define CP_WAIT(n)  asm volatile("cp.async.wait_group %0;" :: "n"(n) : "memory")

// ================= fused permute kernel (x, W1, W2, W3 in one launch) =================
__global__ __launch_bounds__(256) void permute_all(const float* __restrict__ x,
                                                   const float* __restrict__ W1,
                                                   const float* __restrict__ W2,
                                                   const float* __restrict__ W3)
{
    __shared__ float t[64][65];
    const int bid = blockIdx.x;
    const int tid = threadIdx.x;

    if (bid < 512) {
        const int b = bid >> 3, cg = bid & 7;
        #pragma unroll
        for (int i = 0; i < 4; i++) {
            int idx = tid + i * 256;
            int cc = idx >> 4, p4 = (idx & 15) * 4;
            float4 v = *(const float4*)(x + ((size_t)(b * Cn + cg * 64 + cc)) * Pn + p4);
            t[cc][p4 + 0] = v.x; t[cc][p4 + 1] = v.y; t[cc][p4 + 2] = v.z; t[cc][p4 + 3] = v.w;
        }
        __syncthreads();
        #pragma unroll
        for (int i = 0; i < 2; i++) {
            int o = tid + i * 256;
            int lane = o & 31, kbl = (o >> 5) & 3, Rl = (o >> 7) & 3;
            int g = lane >> 2, tt = lane & 3;
            int c0 = kbl * 16 + 2 * tt, pA = Rl * 16 + g;
            uint4 v;
            v.x = pk(t[c0][pA],         t[c0 + 1][pA]);
            v.y = pk(t[c0][pA + 8],     t[c0 + 1][pA + 8]);
            v.z = pk(t[c0 + 8][pA],     t[c0 + 9][pA]);
            v.w = pk(t[c0 + 8][pA + 8], t[c0 + 9][pA + 8]);
            xF[((size_t)(b * 4 + Rl) * 32 + cg * 4 + kbl) * 32 + lane] = v;
        }
    } else if (bid < 2112) {
        int id = (bid - 512) * 256 + tid;
        int lane = id & 31, np = (id >> 5) & 3, kb = (id >> 7) & 31, k = id >> 12;
        int g = lane >> 2, tt = lane & 3;
        int o0 = np * 16 + g, o1 = o0 + 8, c = kb * 16 + 2 * tt;
        const float* W = W1 + (size_t)k * H1n * Cn;
        uint4 v;
        v.x = pk(W[(size_t)o0 * Cn + c],     W[(size_t)o0 * Cn + c + 1]);
        v.y = pk(W[(size_t)o0 * Cn + c + 8], W[(size_t)o0 * Cn + c + 9]);
        v.z = pk(W[(size_t)o1 * Cn + c],     W[(size_t)o1 * Cn + c + 1]);
        v.w = pk(W[(size_t)o1 * Cn + c + 8], W[(size_t)o1 * Cn + c + 9]);
        w1F[id] = v;
    } else if (bid < 2512) {
        int id = (bid - 2112) * 256 + tid;
        int lane = id & 31, np = (id >> 5) & 7, kb = (id >> 8) & 3, k = id >> 10;
        int g = lane >> 2, tt = lane & 3;
        int o0 = np * 16 + g, o1 = o0 + 8, c = kb * 16 + 2 * tt;
        const float* W = W2 + (size_t)k * HIDn * H1n;
        uint4 v;
        v.x = pk(W[(size_t)o0 * H1n + c],     W[(size_t)o0 * H1n + c + 1]);
        v.y = pk(W[(size_t)o0 * H1n + c + 8], W[(size_t)o0 * H1n + c + 9]);
        v.z = pk(W[(size_t)o1 * H1n + c],     W[(size_t)o1 * H1n + c + 1]);
        v.w = pk(W[(size_t)o1 * H1n + c + 8], W[(size_t)o1 * H1n + c + 9]);
        w2F[id] = v;
    } else {
        int id = (bid - 2512) * 256 + tid;
        int lane = id & 31, np = (id >> 5) & 1, kb = (id >> 6) & 7, k = id >> 9;
        int g = lane >> 2, tt = lane & 3;
        int o0 = np * 16 + g, o1 = o0 + 8, c = kb * 16 + 2 * tt;
        const float* W = W3 + (size_t)k * Ln * HIDn;
        uint4 v;
        v.x = pk(W[(size_t)o0 * HIDn + c],     W[(size_t)o0 * HIDn + c + 1]);
        v.y = pk(W[(size_t)o0 * HIDn + c + 8], W[(size_t)o0 * HIDn + c + 9]);
        v.z = pk(W[(size_t)o1 * HIDn + c],     W[(size_t)o1 * HIDn + c + 1]);
        v.w = pk(W[(size_t)o1 * HIDn + c + 8], W[(size_t)o1 * HIDn + c + 9]);
        w3F[id] = v;
    }
}

// ================= main fused kernel: 128 threads, 4 warps, 4 CTAs/SM =================
__global__ __launch_bounds__(128, 4)
void fused_main(const int* __restrict__ ycls, const float* __restrict__ pr0,
                const float* __restrict__ pr1, float* __restrict__ out)
{
    extern __shared__ char smb[];
    const u32 smu = smem_u32(smb);
    const int k     = blockIdx.y;
    const int jtile = blockIdx.x;
    const int jbase = jtile * 128;
    const int b0    = jtile * 2;
    const int tid   = threadIdx.x;
    const int lane  = tid & 31;
    const int warp  = tid >> 5;
    const int g     = lane >> 2;
    const int tt    = lane & 3;

    // ---- prologue cp.async (ONE group): prototype tiles only ----
    {
        const float* p0k = pr0 + (size_t)k * Ln * Pn;
        const float* p1k = pr1 + (size_t)k * Ln * Pn;
        #pragma unroll
        for (int i = 0; i < 4; i++) {
            CP16(smu + PS0 + (tid + i * 128) * 16, p0k + (tid + i * 128) * 4);
            CP16(smu + PS1 + (tid + i * 128) * 16, p1k + (tid + i * 128) * 4);
        }
        CP_COMMIT();
    }

    // ================= Stage A: M=32/warp, N=64, K=512, barrier-free, all-LDG =================
    // Distance-2 prefetch at zero register cost: 2-slot buffers indexed by kb&1;
    // after consuming slot sl at step kb, reload the SAME slot with kb+2.
    const int R0 = jtile * 8 + warp * 2, R1 = R0 + 1;
    const uint4* w1p = w1F + (size_t)k * 4096;   // [kb][np][lane] fragment uint4s
    float accA[8][2][4];
    #pragma unroll
    for (int n = 0; n < 8; n++)
        #pragma unroll
        for (int r = 0; r < 2; r++)
            #pragma unroll
            for (int q = 0; q < 4; q++) accA[n][r][q] = 0.f;

    uint4 aC[2][2];
    uint4 bC[2][4];
    // fill slot 0 (kb=0) and slot 1 (kb=1)
    aC[0][0] = ldg_cg(&xF[((size_t)R0 * 32 + 0) * 32 + lane]);
    aC[0][1] = ldg_cg(&xF[((size_t)R1 * 32 + 0) * 32 + lane]);
    aC[1][0] = ldg_cg(&xF[((size_t)R0 * 32 + 1) * 32 + lane]);
    aC[1][1] = ldg_cg(&xF[((size_t)R1 * 32 + 1) * 32 + lane]);
    #pragma unroll
    for (int np = 0; np < 4; np++) {
        bC[0][np] = w1p[(0 * 4 + np) * 32 + lane];
        bC[1][np] = w1p[(1 * 4 + np) * 32 + lane];
    }

    #pragma unroll
    for (int kb = 0; kb < 32; kb++) {
        const int sl = kb & 1;
        #pragma unroll
        for (int np = 0; np < 4; np++) {
            mma_bf16(accA[2 * np][0],     aC[sl][0], bC[sl][np].x, bC[sl][np].y);
            mma_bf16(accA[2 * np][1],     aC[sl][1], bC[sl][np].x, bC[sl][np].y);
            mma_bf16(accA[2 * np + 1][0], aC[sl][0], bC[sl][np].z, bC[sl][np].w);
            mma_bf16(accA[2 * np + 1][1], aC[sl][1], bC[sl][np].z, bC[sl][np].w);
        }
        if (kb < 30) {                               // same-slot reload at distance 2
            aC[sl][0] = ldg_cg(&xF[((size_t)R0 * 32 + kb + 2) * 32 + lane]);
            aC[sl][1] = ldg_cg(&xF[((size_t)R1 * 32 + kb + 2) * 32 + lane]);
            #pragma unroll
            for (int np = 0; np < 4; np++) bC[sl][np] = w1p[((kb + 2) * 4 + np) * 32 + lane];
        }
    }

    // ---- h1 A-frags in registers ----
    uint4 h1f[2][4];                             // [rt][kb] over K=64
    #pragma unroll
    for (int rt = 0; rt < 2; rt++)
        #pragma unroll
        for (int kb = 0; kb < 4; kb++)
            h1f[rt][kb] = dfrag_to_afrag(accA[2 * kb][rt], accA[2 * kb + 1][rt]);

    // ================= Stages B+C fused: 8 N=16 slices, direct-LDG W2/W3, no barriers ==========
    const uint4* w2p = w2F + (size_t)k * 1024;   // ((kb*8+s)*32+lane)
    const uint4* w3p = w3F + (size_t)k * 512;    // ((s*2+t)*32+lane)
    float accC[4][2][4];
    #pragma unroll
    for (int n = 0; n < 4; n++)
        #pragma unroll
        for (int r = 0; r < 2; r++)
            #pragma unroll
            for (int q = 0; q < 4; q++) accC[n][r][q] = 0.f;

    #pragma unroll
    for (int s = 0; s < 8; s++) {
        // ---- stage B slice: N=16 (h2 cols [16s,16s+16)), K=64 ----
        float accB[2][2][4];
        #pragma unroll
        for (int n = 0; n < 2; n++)
            #pragma unroll
            for (int r = 0; r < 2; r++)
                #pragma unroll
                for (int q = 0; q < 4; q++) accB[n][r][q] = 0.f;
        #pragma unroll
        for (int kb = 0; kb < 4; kb++) {
            uint4 bv = w2p[((size_t)(kb * 8 + s)) * 32 + lane];
            #pragma unroll
            for (int rt = 0; rt < 2; rt++) {
                mma_bf16(accB[0][rt], h1f[rt][kb], bv.x, bv.y);
                mma_bf16(accB[1][rt], h1f[rt][kb], bv.z, bv.w);
            }
        }
        // ---- pack slice as stage-C A-frag (K-chunk s) and accumulate C ----
        uint4 bw0 = w3p[((size_t)(s * 2 + 0)) * 32 + lane];
        uint4 bw1 = w3p[((size_t)(s * 2 + 1)) * 32 + lane];
        #pragma unroll
        for (int rt = 0; rt < 2; rt++) {
            uint4 af = dfrag_to_afrag(accB[0][rt], accB[1][rt]);
            mma_bf16(accC[0][rt], af, bw0.x, bw0.y);
            mma_bf16(accC[1][rt], af, bw0.z, bw0.w);
            mma_bf16(accC[2][rt], af, bw1.x, bw1.y);
            mma_bf16(accC[3][rt], af, bw1.z, bw1.w);
        }
    }

    // ---- first synchronization of the whole kernel: protos landed + visible ----
    CP_WAIT(0);
    __syncthreads();

    // ---- epilogue C: tanh, distances, clip, logits, per-(k,b) sums ----
    {
        const float* ps0 = (const float*)(smb + PS0);   // [32][64] fp32
        const float* ps1 = (const float*)(smb + PS1);
        float* ers  = (float*)(smb + ERS);
        float* er1s = ers + 128;
        #pragma unroll
        for (int rt = 0; rt < 2; rt++) {
            #pragma unroll
            for (int half = 0; half < 2; half++) {
                int lr = warp * 32 + rt * 16 + g + half * 8;
                int p  = (jbase + lr) & 63;
                float d0 = 0.f, d1 = 0.f;
                #pragma unroll
                for (int n0 = 0; n0 < 4; n0++) {
                    int c0 = n0 * 8 + 2 * tt, c1 = c0 + 1;
                    float v0 = tanh_fast(accC[n0][rt][half * 2 + 0]);
                    float v1 = tanh_fast(accC[n0][rt][half * 2 + 1]);
                    float q;
                    q = v0 - ps0[c0 * 64 + p]; d0 += q * q;
                    q = v1 - ps0[c1 * 64 + p]; d0 += q * q;
                    q = v0 - ps1[c0 * 64 + p]; d1 += q * q;
                    q = v1 - ps1[c1 * 64 + p]; d1 += q * q;
                }
                d0 += __shfl_xor_sync(0xFFFFFFFFu, d0, 1);
                d0 += __shfl_xor_sync(0xFFFFFFFFu, d0, 2);
                d1 += __shfl_xor_sync(0xFFFFFFFFu, d1, 1);
                d1 += __shfl_xor_sync(0xFFFFFFFFu, d1, 2);
                if (tt == 0) {
                    float er  = fminf(fmaxf(d0 * REDV, -CLIPV), CLIPV);
                    float er1 = fminf(fmaxf(d1 * REDV, -CLIPV), CLIPV);
                    int b = b0 + (lr >> 6);
                    out[((size_t)b * Kn + k) * Pn + p] = er;
                    out[(size_t)Bn * Kn * Pn + ((size_t)b * Kn + k) * Pn + p] = er1;
                    ers[lr]  = er;
                    er1s[lr] = er1;
                }
            }
        }
    }
    __syncthreads();
    // ---- warp-parallel per-(k,b) sums: warp w -> (array = w<2 ? er : er1, b = b0 + (w&1)) ----
    if (warp < 4) {
        const float* src = (float*)(smb + ERS) + ((warp < 2) ? 0 : 128) + (warp & 1) * 64;
        float s = src[lane] + src[lane + 32];
        #pragma unroll
        for (int m = 16; m > 0; m >>= 1) s += __shfl_xor_sync(0xFFFFFFFFu, s, m);
        if (lane == 0) {
            if (warp < 2) f_dev[k * Bn + b0 + (warp & 1)]  = s;
            else          f1_dev[k * Bn + b0 + (warp & 1)] = s;
        }
    }
    __syncthreads();

    // ---- last-CTA finalize: pull/push ----
    __threadfence();
    __shared__ u32 s_is_last;
    if (tid == 0) {
        u32 old = atomicAdd(&done_ctr, 1u);
        s_is_last = (old == gridDim.x * gridDim.y - 1) ? 1u : 0u;
    }
    __syncthreads();
    if (s_is_last) {
        __threadfence();
        float* s_pull = (float*)smb;
        float* s_push = s_pull + 128;
        float pull = 0.f, push = 0.f;
        if (tid < Kn) {
            float se = 0.f, sc = 0.f;
            int ne = 0, nc = 0;
            #pragma unroll 8
            for (int b = 0; b < Bn; b++) {
                float fv  = __ldcg(&f_dev[tid * Bn + b]);
                float f1v = __ldcg(&f1_dev[tid * Bn + b]);
                if (ycls[b] == tid) { se += f1v; ne++; }
                else if (fv < PUSHT) { sc += fv; nc++; }
            }
            if (ne > 0) pull = se / (float)ne;
            if (nc > 0) push = sc / (float)nc;
        }
        s_pull[tid] = pull;
        s_push[tid] = push;
        __syncthreads();
        for (int s = 64; s > 0; s >>= 1) {
            if (tid < s) { s_pull[tid] += s_pull[tid + s]; s_push[tid] += s_push[tid + s]; }
            __syncthreads();
        }
        if (tid == 0) {
            size_t base = (size_t)2 * Bn * Kn * Pn;
            out[base]     = s_pull[0];
            out[base + 1] = s_push[0];
            done_ctr = 0;   // deterministic across graph replays
        }
    }
}

extern "C" void kernel_launch(void* const* d_in, const int* in_sizes, int n_in,
                              void* d_out, int out_size)
{
    const float* x    = (const float*)d_in[0];
    const int*   ycls = (const int*)  d_in[1];
    const float* W1   = (const float*)d_in[4];
    const float* W2   = (const float*)d_in[5];
    const float* W3   = (const float*)d_in[6];
    const float* pr0  = (const float*)d_in[7];
    const float* pr1  = (const float*)d_in[8];
    float* out = (float*)d_out;

    permute_all<<<2712, 256>>>(x, W1, W2, W3);

    cudaFuncSetAttribute(fused_main, cudaFuncAttributeMaxDynamicSharedMemorySize, SMEM_BYTES);
    fused_main<<<dim3(32, Kn), 128, SMEM_BYTES>>>(ycls, pr0, pr1, out);
}